// round 17
// baseline (speedup 1.0000x reference)
#include <cuda_runtime.h>
#include <cuda_bf16.h>
#include <cstdint>

// Problem constants
#define MDIM 16384
#define NDIM 16384
#define KDIM 512
#define ALPHA_C 0.1f
#define NU_C 1e-3f

#define MT 128
#define NT 32                        // per-quarter tile width
#define NPC 2048                     // N-cols per CTA
#define QTILES 16                    // (2048/4)/32 tiles per quarter
#define UNITS 1024                   // grid size: 128 m-tiles x 8 n-units

// smem layout (bytes)
#define SM_A   0                     // 8 chunks x [128 x 128B] SW128 = 131072
#define SM_B   131072                // 4 quarters x 4 slots x 4096 = 65536
#define SM_M2  196608                // [4 quarters][2 mb][32] floats = 1024
#define SM_STG 197632                // 128 x 24 floats = 12288
#define SMEM_BYTES 209920

// Scratch
__device__ __align__(16) __nv_bfloat16 g_A [MDIM * KDIM];
__device__ __align__(16) __nv_bfloat16 g_Bm[NDIM * KDIM];
__device__ float g_x2[MDIM];
__device__ float g_m2[NDIM];
__device__ float g_top6[UNITS * 128 * 6];
__device__ float g_part[MDIM / MT];

// ---------------- PTX helpers ----------------
#define CP16(dst, src) \
  asm volatile("cp.async.cg.shared.global [%0], [%1], 16;\n" :: "r"(dst), "l"(src))
#define CP_COMMIT() asm volatile("cp.async.commit_group;\n" ::: "memory")
#define CP_WAIT(n)  asm volatile("cp.async.wait_group %0;\n" :: "n"(n) : "memory")

#define BAR_Q(id) asm volatile("bar.sync %0, 128;" :: "r"(id) : "memory")

#define LDSM4(R0, R1, R2, R3, ADDR) \
  asm volatile("ldmatrix.sync.aligned.m8n8.x4.shared.b16 {%0,%1,%2,%3}, [%4];" \
               : "=r"(R0), "=r"(R1), "=r"(R2), "=r"(R3) : "r"(ADDR))

#define MMA16816(C, A, B0, B1) \
  asm volatile("mma.sync.aligned.m16n8k16.row.col.f32.bf16.bf16.f32 " \
               "{%0,%1,%2,%3},{%4,%5,%6,%7},{%8,%9},{%0,%1,%2,%3};" \
               : "+f"((C)[0]), "+f"((C)[1]), "+f"((C)[2]), "+f"((C)[3]) \
               : "r"((A)[0]), "r"((A)[1]), "r"((A)[2]), "r"((A)[3]), \
                 "r"(B0), "r"(B1))

#define SWZ128(x) ((x) ^ (((x) >> 3) & 0x70))

// ---------------- Prep kernels ----------------
// Fused transpose + x2: one block owns 32 hw-rows x all 512 channels.
__global__ void prep_phi_x2(const float* __restrict__ phi) {
    __shared__ float t[32][33];
    __shared__ float x2s[32];
    const int b = blockIdx.y, h0 = blockIdx.x * 32;
    const int tx = threadIdx.x, ty = threadIdx.y;
    const int tid = tx + ty * 32;
    if (tid < 32) x2s[tid] = 0.f;
    __syncthreads();

#pragma unroll 1
    for (int cb = 0; cb < 16; cb++) {
        const int c0 = cb * 32;
        const float* p = phi + ((size_t)b * 512 + c0) * 4096 + h0;
#pragma unroll
        for (int i = 0; i < 4; i++)
            t[ty + 8 * i][tx] = p[(size_t)(ty + 8 * i) * 4096 + tx];
        __syncthreads();
#pragma unroll
        for (int i = 0; i < 4; i++) {
            int row = ty + 8 * i;
            float v = t[tx][row];
            g_A[((size_t)b * 4096 + h0 + row) * 512 + c0 + tx] = __float2bfloat16(v);
            float sq = v * v;
#pragma unroll
            for (int o = 16; o > 0; o >>= 1) sq += __shfl_xor_sync(0xffffffffu, sq, o);
            if (tx == 0) x2s[row] += sq;
        }
        __syncthreads();
    }
    if (tid < 32) g_x2[(size_t)b * 4096 + h0 + tid] = x2s[tid];
}

__global__ void prep_mem(const float* __restrict__ mem) {
    int row  = (blockIdx.x * 256 + threadIdx.x) >> 5;
    int lane = threadIdx.x & 31;
    const float* p = mem + (size_t)row * 512;
    __nv_bfloat16* q = g_Bm + (size_t)row * 512;
    float s = 0.f;
#pragma unroll
    for (int i = 0; i < 16; i++) {
        float v = p[lane + i * 32];
        q[lane + i * 32] = __float2bfloat16(v);
        s = fmaf(v, v, s);
    }
#pragma unroll
    for (int o = 16; o > 0; o >>= 1) s += __shfl_xor_sync(0xffffffffu, s, o);
    if (lane == 0) g_m2[row] = s;
}

// ---------------- Main fused kernel ----------------
__device__ __forceinline__ void insert6a(float v, float (&q)[6]) {
    if (v < q[5]) {
        q[5] = v;
        if (q[5] < q[4]) { float t = q[4]; q[4] = q[5]; q[5] = t;
            if (q[4] < q[3]) { t = q[3]; q[3] = q[4]; q[4] = t;
                if (q[3] < q[2]) { t = q[2]; q[2] = q[3]; q[3] = t;
                    if (q[2] < q[1]) { t = q[1]; q[1] = q[2]; q[2] = t;
                        if (q[1] < q[0]) { t = q[0]; q[0] = q[1]; q[1] = t; } } } } }
    }
}

// stage s (k-chunk of 64 bf16) of 32-row tile n0 into quarter's ring slot
__device__ __forceinline__ void b_stage(uint32_t bOffQ, int slot, int n0, int s, int tidq) {
#pragma unroll
    for (int i = 0; i < 2; i++) {
        int c = tidq + i * 128;               // 256 16B-units: 32 rows x 8 segs
        int row = c >> 3, seg = c & 7;
        uint32_t dst = bOffQ + (uint32_t)(slot * 4096 + SWZ128(row * 128 + seg * 16));
        CP16(dst, g_Bm + (size_t)(n0 + row) * KDIM + s * 64 + seg * 8);
    }
}

__global__ __launch_bounds__(512, 1)
void knn_gemm(void) {
    extern __shared__ char smem[];
    float* m2s   = (float*)(smem + SM_M2);    // [quarter][mb][32]
    float* stage = (float*)(smem + SM_STG);

    const int tid  = threadIdx.x;
    const int lane = tid & 31;
    const int warp = tid >> 5;
    const int qtr  = warp >> 2;               // 0..3
    const int wm   = warp & 3;                // 4 warps along M within quarter
    const int tidq = tid & 127;
    const int m0     = (blockIdx.x >> 3) * MT;
    const int nqbase = (blockIdx.x & 7) * NPC + qtr * (NPC / 4);

    uint32_t sbase = (uint32_t)__cvta_generic_to_shared(smem);
    const uint32_t aOff  = sbase + SM_A;
    const uint32_t bOffQ = sbase + SM_B + qtr * 16384;

    // ldmatrix lane mappings (verified R2..R16)
    const int aRow    = wm * 32 + (lane & 15);
    const int aColSel = ((lane >> 4) & 1) * 8;
    const int bRow    = (lane & 7) + ((lane >> 4) & 1) * 8;
    const int bColSel = ((lane >> 3) & 1) * 8;

    const int g  = lane >> 2;
    const int qd = lane & 3;

    float x2v[2][2];
#pragma unroll
    for (int mi = 0; mi < 2; mi++)
#pragma unroll
        for (int p = 0; p < 2; p++)
            x2v[mi][p] = g_x2[m0 + wm * 32 + mi * 16 + g + p * 8];

    // ---- A load (full CTA): 8 chunks x [128 x 128B] SW128
#pragma unroll
    for (int i = 0; i < 16; i++) {
        int c = tid + i * 512;
        int chunk = c >> 10, u = c & 1023;
        int row = u >> 3, seg = u & 7;
        uint32_t dst = aOff + (uint32_t)(chunk * 16384 + SWZ128(row * 128 + seg * 16));
        CP16(dst, g_A + (size_t)(m0 + row) * KDIM + chunk * 64 + seg * 8);
    }
    CP_COMMIT();
    // ---- per-quarter B ring prologue: stages 0,1,2 of quarter's tile 0
    b_stage(bOffQ, 0, nqbase, 0, tidq); CP_COMMIT();
    b_stage(bOffQ, 1, nqbase, 1, tidq); CP_COMMIT();
    b_stage(bOffQ, 2, nqbase, 2, tidq); CP_COMMIT();

    // A must be fully visible to ALL quarters before mainloop
    CP_WAIT(3);
    __syncthreads();

    float ql[2][2][6];
#pragma unroll
    for (int mi = 0; mi < 2; mi++)
#pragma unroll
        for (int p = 0; p < 2; p++)
#pragma unroll
            for (int j = 0; j < 6; j++) ql[mi][p][j] = INFINITY;

    float acc[2][4][4];
#pragma unroll
    for (int mi = 0; mi < 2; mi++)
#pragma unroll
        for (int ni = 0; ni < 4; ni++)
#pragma unroll
            for (int r = 0; r < 4; r++) acc[mi][ni][r] = 0.f;

    const int barid = 1 + qtr;

    // ---- main loop: 16 tiles (32 cols each) x 8 compile-time stages ----
#pragma unroll 1
    for (int nt = 0; nt < QTILES; nt++) {
        const int mb = nt & 1;
        const int n0 = nqbase + nt * NT;
        if (tidq < 32) m2s[qtr * 64 + mb * 32 + tidq] = g_m2[n0 + tidq];

#pragma unroll
        for (int s = 0; s < 8; s++) {
            CP_WAIT(2);
            BAR_Q(barid);

            const uint32_t bbuf = bOffQ + (s & 3) * 4096;   // compile-time offset
            const uint32_t abuf = aOff + s * 16384;         // compile-time offset
#pragma unroll
            for (int kk = 0; kk < 64; kk += 16) {
                uint32_t a[2][4], bf[4][2];
#pragma unroll
                for (int mi = 0; mi < 2; mi++) {
                    uint32_t ad = abuf + (uint32_t)SWZ128(((aRow + mi * 16) * 128 + (kk + aColSel) * 2));
                    LDSM4(a[mi][0], a[mi][1], a[mi][2], a[mi][3], ad);
                }
#pragma unroll
                for (int jp = 0; jp < 2; jp++) {
                    uint32_t bd = bbuf + (uint32_t)SWZ128(((bRow + jp * 16) * 128 + (kk + bColSel) * 2));
                    LDSM4(bf[2 * jp][0], bf[2 * jp][1], bf[2 * jp + 1][0], bf[2 * jp + 1][1], bd);
                }
#pragma unroll
                for (int mi = 0; mi < 2; mi++)
#pragma unroll
                    for (int ni = 0; ni < 4; ni++)
                        MMA16816(acc[mi][ni], a[mi], bf[ni][0], bf[ni][1]);
            }

            // prefetch stage gg+3 of this quarter (compile-time slot/stage)
            {
                const int nt3 = nt + ((s + 3) >> 3);
                if (nt3 < QTILES)
                    b_stage(bOffQ, (s + 3) & 3, nqbase + nt3 * NT, (s + 3) & 7, tidq);
            }
            CP_COMMIT();

            if (s == 7) {
                // in-register epilogue: 16 distances into 4 running lists
#pragma unroll
                for (int mi = 0; mi < 2; mi++)
#pragma unroll
                    for (int ni = 0; ni < 4; ni++) {
                        const int col = ni * 8 + 2 * qd;             // 0..31 in tile
                        const float m20 = m2s[qtr * 64 + mb * 32 + col];
                        const float m21 = m2s[qtr * 64 + mb * 32 + col + 1];
                        insert6a(fmaxf(fmaf(-2.f, acc[mi][ni][0], x2v[mi][0] + m20), 0.f), ql[mi][0]);
                        insert6a(fmaxf(fmaf(-2.f, acc[mi][ni][1], x2v[mi][0] + m21), 0.f), ql[mi][0]);
                        insert6a(fmaxf(fmaf(-2.f, acc[mi][ni][2], x2v[mi][1] + m20), 0.f), ql[mi][1]);
                        insert6a(fmaxf(fmaf(-2.f, acc[mi][ni][3], x2v[mi][1] + m21), 0.f), ql[mi][1]);
                        acc[mi][ni][0] = 0.f; acc[mi][ni][1] = 0.f;
                        acc[mi][ni][2] = 0.f; acc[mi][ni][3] = 0.f;
                    }
            }
        }
    }

    // ---- quad merge (same 4 rows within a quad), snapshot-before-insert
#pragma unroll
    for (int off = 2; off > 0; off >>= 1) {
#pragma unroll
        for (int mi = 0; mi < 2; mi++)
#pragma unroll
            for (int p = 0; p < 2; p++) {
                float t[6];
#pragma unroll
                for (int j = 0; j < 6; j++)
                    t[j] = __shfl_down_sync(0xffffffffu, ql[mi][p][j], off, 4);
#pragma unroll
                for (int j = 0; j < 6; j++) insert6a(t[j], ql[mi][p]);
            }
    }

    // ---- cross merge staging: 4 lists/row = quarter, 6 values each
    if (qd == 0) {
#pragma unroll
        for (int mi = 0; mi < 2; mi++)
#pragma unroll
            for (int p = 0; p < 2; p++) {
                int r = wm * 32 + mi * 16 + g + p * 8;
#pragma unroll
                for (int j = 0; j < 6; j++)
                    stage[r * 24 + qtr * 6 + j] = ql[mi][p][j];
            }
    }
    __syncthreads();

    // per-row top-6 of this unit -> g_top6[blockIdx.x]
    if (tid < 128) {
        float f[6] = {INFINITY, INFINITY, INFINITY, INFINITY, INFINITY, INFINITY};
        const float* sr = stage + tid * 24;
#pragma unroll
        for (int i = 0; i < 24; i++) insert6a(sr[i], f);
        float* dst = g_top6 + ((size_t)blockIdx.x * 128 + tid) * 6;
#pragma unroll
        for (int j = 0; j < 6; j++) dst[j] = f[j];
    }
}

// Merge 8 unit-partials per row, hinge, per-m-tile reduce
__global__ void finalize_top(const float* __restrict__ rptr) {
    __shared__ float red[128];
    const int b = blockIdx.x;     // m-tile
    const int t = threadIdx.x;    // row
    float f[6] = {INFINITY, INFINITY, INFINITY, INFINITY, INFINITY, INFINITY};
    const float* base = g_top6 + ((size_t)b * 8 * 128 + t) * 6;
#pragma unroll
    for (int j = 0; j < 8; j++) {
        const float* src = base + (size_t)j * 128 * 6;
#pragma unroll
        for (int k = 0; k < 6; k++) insert6a(src[k], f);
    }
    float rv = rptr[0];
    float r2 = rv * rv;
    float part = fmaxf(f[0] - r2, 0.f) + fmaxf(f[1] - r2, 0.f) + fmaxf(f[2] - r2, 0.f)
               + fmaxf(r2 - f[3] - ALPHA_C, 0.f) + fmaxf(r2 - f[4] - ALPHA_C, 0.f)
               + fmaxf(r2 - f[5] - ALPHA_C, 0.f);
    red[t] = part;
    __syncthreads();
#pragma unroll
    for (int o = 64; o > 0; o >>= 1) {
        if (t < o) red[t] += red[t + o];
        __syncthreads();
    }
    if (t == 0) g_part[b] = red[0];
}

// Deterministic final reduction
__global__ void finalize_loss(float* __restrict__ out) {
    __shared__ float s[128];
    int t = threadIdx.x;
    s[t] = g_part[t];
    __syncthreads();
#pragma unroll
    for (int o = 64; o > 0; o >>= 1) {
        if (t < o) s[t] += s[t + o];
        __syncthreads();
    }
    if (t == 0) out[0] = s[0] * (1.0f / (49152.0f * NU_C));
}

// ---------------- launch ----------------
extern "C" void kernel_launch(void* const* d_in, const int* in_sizes, int n_in,
                              void* d_out, int out_size) {
    (void)in_sizes; (void)n_in; (void)out_size;
    const float* phi = (const float*)d_in[0];
    const float* mem = (const float*)d_in[1];
    const float* r   = (const float*)d_in[2];
    float* out = (float*)d_out;

    cudaFuncSetAttribute(knn_gemm, cudaFuncAttributeMaxDynamicSharedMemorySize, SMEM_BYTES);

    prep_phi_x2<<<dim3(128, 4), dim3(32, 8)>>>(phi);
    prep_mem<<<NDIM / 8, 256>>>(mem);
    knn_gemm<<<UNITS, 512, SMEM_BYTES>>>();
    finalize_top<<<MDIM / MT, 128>>>(r);
    finalize_loss<<<1, 128>>>(out);
}